// round 3
// baseline (speedup 1.0000x reference)
#include <cuda_runtime.h>
#include <cstdint>

#define SEQ 32
#define HD  2048

// ---------------- scratch (device globals; no allocation) ----------------
__device__ float g_x   [HD  * SEQ];    // residual stream, feature-major [k][s]
__device__ float g_qkv [6144* SEQ];
__device__ float g_t8  [8192* SEQ];
__device__ float g_t2  [HD  * SEQ];
__device__ float g_vc  [HD];
__device__ float g_cc  [HD];
__device__ float g_h1  [1024];
__device__ float g_parts[16 * SEQ * 2];
__device__ float g_gp  [1u << 20];     // split-K partials (4 MB)

// ---------------- GEMM: out_part[kz][n][s] = sum_k W[n,k]*A[k][s] --------
// A is feature-major [K][32]. W row-major [N][K]. Partial over a K slice.
#define GNPW 16            // n-rows per warp
#define GBN  128           // n-rows per block (8 warps)
#define GKS  64            // k-chunk staged in smem

__global__ void __launch_bounds__(256) k_gemm(
    const float* __restrict__ W, const float* __restrict__ A,
    float* __restrict__ part, int N, int K, int Kper)
{
    __shared__ float ws[GBN][GKS];   // 32 KB
    __shared__ float xs[GKS][SEQ];   //  8 KB
    const int nb   = blockIdx.x * GBN;
    const int tid  = threadIdx.x;
    const int lane = tid & 31;
    const int wid  = tid >> 5;
    const int kbeg = blockIdx.y * Kper;

    unsigned long long acc[GNPW];
#pragma unroll
    for (int j = 0; j < GNPW; j++) acc[j] = 0ull;

    for (int k0 = kbeg; k0 < kbeg + Kper; k0 += GKS) {
        __syncthreads();
        // stage x chunk: contiguous 64*32 floats
        {
            const float4* src = (const float4*)(A + (size_t)k0 * SEQ);
            float4* dst = (float4*)&xs[0][0];
            dst[tid]       = src[tid];
            dst[tid + 256] = src[tid + 256];
        }
        // stage weight tile: 128 rows x 64 floats
#pragma unroll
        for (int i = 0; i < 8; i++) {
            int idx = tid + i * 256;
            int n   = idx >> 4;       // 16 float4 per row
            int kv  = idx & 15;
            float4 v = *(const float4*)(W + (size_t)(nb + n) * K + k0 + kv * 4);
            *(float4*)&ws[n][kv * 4] = v;
        }
        __syncthreads();

        const int nwb = wid * GNPW;
        for (int kk = 0; kk < GKS; kk += 4) {
            float x0 = xs[kk][lane], x1 = xs[kk + 1][lane];
            float x2 = xs[kk + 2][lane], x3 = xs[kk + 3][lane];
            unsigned long long xA, xB;
            asm("mov.b64 %0,{%1,%2};" : "=l"(xA) : "f"(x0), "f"(x1));
            asm("mov.b64 %0,{%1,%2};" : "=l"(xB) : "f"(x2), "f"(x3));
#pragma unroll
            for (int j = 0; j < GNPW; j++) {
                float4 w = *(const float4*)&ws[nwb + j][kk];   // uniform -> broadcast LDS
                unsigned long long wA, wB;
                asm("mov.b64 %0,{%1,%2};" : "=l"(wA) : "f"(w.x), "f"(w.y));
                asm("mov.b64 %0,{%1,%2};" : "=l"(wB) : "f"(w.z), "f"(w.w));
                asm("fma.rn.f32x2 %0,%1,%2,%0;" : "+l"(acc[j]) : "l"(wA), "l"(xA));
                asm("fma.rn.f32x2 %0,%1,%2,%0;" : "+l"(acc[j]) : "l"(wB), "l"(xB));
            }
        }
    }
#pragma unroll
    for (int j = 0; j < GNPW; j++) {
        int n = nb + wid * GNPW + j;
        float lo, hi;
        asm("mov.b64 {%0,%1},%2;" : "=f"(lo), "=f"(hi) : "l"(acc[j]));
        part[((size_t)blockIdx.y * N + n) * SEQ + lane] = lo + hi;
    }
}

// reduce split-K partials + bias + optional gelu; out_mode 0: [n][32], 1: d_out row-major [s][N]
__global__ void k_gemm_red(const float* __restrict__ part, const float* __restrict__ bias,
                           float* __restrict__ out, int N, int kspl, int act, int out_mode)
{
    int idx = blockIdx.x * 256 + threadIdx.x;
    if (idx >= N * SEQ) return;
    int n = idx >> 5, s = idx & 31;
    float v = bias[n];
    for (int z = 0; z < kspl; z++) v += part[(size_t)z * N * SEQ + idx];
    if (act == 1) v = v * normcdff(v);
    if (out_mode == 0) out[idx] = v;
    else               out[(size_t)s * N + n] = v;
}

// ---------------- GEMV: vout[n] = act(W[n,:].vin + b[n]) -----------------
__global__ void k_gemv(const float* __restrict__ W, const float* __restrict__ bias,
                       const float* __restrict__ vin, float* __restrict__ vout,
                       int K, int act)
{
    int n    = blockIdx.x * 8 + (threadIdx.x >> 5);
    int lane = threadIdx.x & 31;
    const float* wr = W + (size_t)n * K;
    float s = 0.f;
    for (int k = lane * 4; k < K; k += 128) {
        float4 w = *(const float4*)(wr + k);
        float4 x = *(const float4*)(vin + k);
        s += w.x * x.x + w.y * x.y + w.z * x.z + w.w * x.w;
    }
#pragma unroll
    for (int o = 16; o; o >>= 1) s += __shfl_xor_sync(~0u, s, o);
    if (lane == 0) {
        float v = s + bias[n];
        if (act) v = v * normcdff(v);
        vout[n] = v;
    }
}

// ---------------- size-predictor head: 33-way logits + softmax -----------
__global__ void k_sp2(const float* __restrict__ w2, const float* __restrict__ b2,
                      const float* __restrict__ h1, float* __restrict__ outp)
{
    __shared__ float lg[33];
    int lane = threadIdx.x & 31, wid = threadIdx.x >> 5;
    for (int j = wid; j < 33; j += 8) {
        const float* wr = w2 + (size_t)j * 1024;
        float s = 0.f;
        for (int k = lane * 4; k < 1024; k += 128) {
            float4 w = *(const float4*)(wr + k);
            float4 x = *(const float4*)(h1 + k);
            s += w.x * x.x + w.y * x.y + w.z * x.z + w.w * x.w;
        }
#pragma unroll
        for (int o = 16; o; o >>= 1) s += __shfl_xor_sync(~0u, s, o);
        if (lane == 0) lg[j] = s + b2[j];
    }
    __syncthreads();
    if (threadIdx.x == 0) {
        float m = lg[0];
        for (int j = 1; j < 33; j++) m = fmaxf(m, lg[j]);
        float e[33], se = 0.f;
        for (int j = 0; j < 33; j++) { e[j] = expf(lg[j] - m); se += e[j]; }
        float inv = 1.f / se;
        for (int j = 0; j < 33; j++) outp[j] = e[j] * inv;
    }
}

// ---------------- embedding: x[k][s] = byte_emb[dec[s]][k] + pos_emb[s][k]
__global__ void k_embed(const int* __restrict__ tb, const float* __restrict__ bemb,
                        const float* __restrict__ pemb, float* __restrict__ x)
{
    int idx = blockIdx.x * 256 + threadIdx.x;   // s*H + k
    int s = idx >> 11, k = idx & 2047;
    int d = (s == 0) ? 256 : tb[s - 1];
    x[(size_t)k * SEQ + s] = bemb[(size_t)d * HD + k] + pemb[idx];
}

// ---------------- self-attention, one block per head ---------------------
__global__ void __launch_bounds__(256) k_attn(const float* __restrict__ qkv,
                                              float* __restrict__ o)
{
    __shared__ float qs[128][SEQ], ksm[128][SEQ], sc[SEQ][SEQ + 1];
    const int h = blockIdx.x, t = threadIdx.x;
    const int base_q = (h * 256) * SEQ;
    const int base_k = (2048 + h * 256) * SEQ;
    const int base_v = (4096 + h * 256) * SEQ;
    float p0 = 0, p1 = 0, p2 = 0, p3 = 0;

    for (int dc = 0; dc < 256; dc += 128) {
        __syncthreads();
        const float4* q4 = (const float4*)(qkv + base_q + dc * SEQ);
        const float4* k4 = (const float4*)(qkv + base_k + dc * SEQ);
        float4* qd = (float4*)&qs[0][0];
        float4* kd = (float4*)&ksm[0][0];
#pragma unroll
        for (int i = 0; i < 4; i++) { qd[t + i*256] = q4[t + i*256]; kd[t + i*256] = k4[t + i*256]; }
        __syncthreads();
        int qi0 = t >> 5, ki = t & 31;
        for (int d = 0; d < 128; d++) {
            float kv = ksm[d][ki];
            p0 += qs[d][qi0     ] * kv;
            p1 += qs[d][qi0 +  8] * kv;
            p2 += qs[d][qi0 + 16] * kv;
            p3 += qs[d][qi0 + 24] * kv;
        }
    }
    {
        int qi0 = t >> 5, ki = t & 31;
        sc[qi0     ][ki] = p0 * 0.0625f;
        sc[qi0 +  8][ki] = p1 * 0.0625f;
        sc[qi0 + 16][ki] = p2 * 0.0625f;
        sc[qi0 + 24][ki] = p3 * 0.0625f;
    }
    __syncthreads();
    {
        int wid = t >> 5, lane = t & 31;
        for (int qi = wid; qi < SEQ; qi += 8) {
            float v = sc[qi][lane];
            float m = v;
#pragma unroll
            for (int off = 16; off; off >>= 1) m = fmaxf(m, __shfl_xor_sync(~0u, m, off));
            float e = expf(v - m);
            float ss = e;
#pragma unroll
            for (int off = 16; off; off >>= 1) ss += __shfl_xor_sync(~0u, ss, off);
            sc[qi][lane] = e / ss;
        }
    }
    for (int dc = 0; dc < 256; dc += 128) {
        __syncthreads();
        const float4* v4 = (const float4*)(qkv + base_v + dc * SEQ);
        float4* vd = (float4*)&qs[0][0];
#pragma unroll
        for (int i = 0; i < 4; i++) vd[t + i*256] = v4[t + i*256];
        __syncthreads();
#pragma unroll
        for (int i = 0; i < 16; i++) {
            int idx = t + i * 256;
            int d = idx >> 5, qi = idx & 31;
            float a = 0.f;
#pragma unroll
            for (int ki = 0; ki < SEQ; ki++) a += sc[qi][ki] * qs[d][ki];
            o[(size_t)(h * 256 + dc + d) * SEQ + qi] = a;
        }
    }
}

// ---------------- LayerNorm (residual fused), two stages -----------------
// stage 1: z = x + add (matrix or broadcast vec); x<-z; per-token partial stats
__global__ void k_ln_part(float* __restrict__ x, const float* __restrict__ add,
                          int vecmode, float* __restrict__ parts)
{
    __shared__ float rs[8][SEQ], rq[8][SEQ];
    int b = blockIdx.x, t = threadIdx.x;
    int s = t & 31, kr = t >> 5;
    float sum = 0, sq = 0;
#pragma unroll
    for (int i = 0; i < 16; i++) {
        int k = b * 128 + i * 8 + kr;
        int idx = k * SEQ + s;
        float z = x[idx] + (vecmode ? add[k] : add[idx]);
        x[idx] = z;
        sum += z; sq += z * z;
    }
    rs[kr][s] = sum; rq[kr][s] = sq;
    __syncthreads();
    if (t < 32) {
        float a = 0, q = 0;
#pragma unroll
        for (int r = 0; r < 8; r++) { a += rs[r][t]; q += rq[r][t]; }
        parts[(b * SEQ + t) * 2]     = a;
        parts[(b * SEQ + t) * 2 + 1] = q;
    }
}
// stage 2: normalize with gamma/beta
__global__ void k_ln_apply(float* __restrict__ x, const float* __restrict__ g,
                           const float* __restrict__ bb, const float* __restrict__ parts)
{
    __shared__ float mean[SEQ], rstd[SEQ];
    int t = threadIdx.x;
    if (t < 32) {
        float a = 0, q = 0;
#pragma unroll
        for (int b = 0; b < 16; b++) { a += parts[(b * SEQ + t) * 2]; q += parts[(b * SEQ + t) * 2 + 1]; }
        float m = a * (1.0f / 2048.0f);
        float v = q * (1.0f / 2048.0f) - m * m;
        mean[t] = m;
        rstd[t] = rsqrtf(v + 1e-5f);
    }
    __syncthreads();
    int base = blockIdx.x * 1024;
#pragma unroll
    for (int i = 0; i < 4; i++) {
        int idx = base + t + i * 256;
        int k = idx >> 5, s = idx & 31;
        x[idx] = (x[idx] - mean[s]) * rstd[s] * g[k] + bb[k];
    }
}

// ---------------- host-side orchestration --------------------------------
static void run_gemm(const float* W, const float* bias, const float* A, float* out,
                     int N, int K, int kspl, int act, int out_mode, float* gp)
{
    dim3 grid(N / GBN, kspl);
    k_gemm<<<grid, 256>>>(W, A, gp, N, K, K / kspl);
    k_gemm_red<<<(N * SEQ + 255) / 256, 256>>>(gp, bias, out, N, kspl, act, out_mode);
}

extern "C" void kernel_launch(void* const* d_in, const int* in_sizes, int n_in,
                              void* d_out, int out_size)
{
    const float* pe      = (const float*)d_in[0];
    const int*   tb      = (const int*)  d_in[1];
    const float* sp_w1   = (const float*)d_in[2];
    const float* sp_b1   = (const float*)d_in[3];
    const float* sp_w2   = (const float*)d_in[4];
    const float* sp_b2   = (const float*)d_in[5];
    const float* bemb    = (const float*)d_in[6];
    const float* pemb    = (const float*)d_in[7];
    const float* proj_w  = (const float*)d_in[8];
    const float* proj_b  = (const float*)d_in[9];
    const float* sa_in_w = (const float*)d_in[10];
    const float* sa_in_b = (const float*)d_in[11];
    const float* sa_out_w= (const float*)d_in[12];
    const float* sa_out_b= (const float*)d_in[13];
    const float* ca_in_w = (const float*)d_in[14];
    const float* ca_in_b = (const float*)d_in[15];
    const float* ca_out_w= (const float*)d_in[16];
    const float* ca_out_b= (const float*)d_in[17];
    const float* ff_w1   = (const float*)d_in[18];
    const float* ff_b1   = (const float*)d_in[19];
    const float* ff_w2   = (const float*)d_in[20];
    const float* ff_b2   = (const float*)d_in[21];
    const float* ln1_g   = (const float*)d_in[22];
    const float* ln1_b   = (const float*)d_in[23];
    const float* ln2_g   = (const float*)d_in[24];
    const float* ln2_b   = (const float*)d_in[25];
    const float* ln3_g   = (const float*)d_in[26];
    const float* ln3_b   = (const float*)d_in[27];
    float* out = (float*)d_out;

    float *xp, *qkvp, *t8, *t2, *vc, *cc, *h1, *parts, *gp;
    cudaGetSymbolAddress((void**)&xp,    g_x);
    cudaGetSymbolAddress((void**)&qkvp,  g_qkv);
    cudaGetSymbolAddress((void**)&t8,    g_t8);
    cudaGetSymbolAddress((void**)&t2,    g_t2);
    cudaGetSymbolAddress((void**)&vc,    g_vc);
    cudaGetSymbolAddress((void**)&cc,    g_cc);
    cudaGetSymbolAddress((void**)&h1,    g_h1);
    cudaGetSymbolAddress((void**)&parts, g_parts);
    cudaGetSymbolAddress((void**)&gp,    g_gp);

    // size-predictor head -> out[0:33]
    k_gemv<<<1024 / 8, 256>>>(sp_w1, sp_b1, pe, h1, HD, 1);
    k_sp2 <<<1, 256>>>(sp_w2, sp_b2, h1, out);

    // byte+pos embedding -> g_x (feature-major)
    k_embed<<<(SEQ * HD) / 256, 256>>>(tb, bemb, pemb, xp);

    for (int i = 0; i < 3; i++) {
        const float* saw  = sa_in_w  + (size_t)i * 6144 * HD;
        const float* sab  = sa_in_b  + (size_t)i * 6144;
        const float* sow  = sa_out_w + (size_t)i * HD * HD;
        const float* sob  = sa_out_b + (size_t)i * HD;
        const float* cawv = ca_in_w  + (size_t)i * 6144 * HD + (size_t)4096 * HD; // Wv only
        const float* cabv = ca_in_b  + (size_t)i * 6144 + 4096;
        const float* cow  = ca_out_w + (size_t)i * HD * HD;
        const float* cob  = ca_out_b + (size_t)i * HD;
        const float* f1w  = ff_w1 + (size_t)i * 8192 * HD;
        const float* f1b  = ff_b1 + (size_t)i * 8192;
        const float* f2w  = ff_w2 + (size_t)i * HD * 8192;
        const float* f2b  = ff_b2 + (size_t)i * HD;

        // --- self-attention ---
        run_gemm(saw, sab, xp, qkvp, 6144, HD, 4, 0, 0, gp);
        k_attn<<<8, 256>>>(qkvp, t2);
        run_gemm(sow, sob, t2, t8, HD, HD, 8, 0, 0, gp);
        k_ln_part <<<16, 256>>>(xp, t8, 0, parts);
        k_ln_apply<<<64, 256>>>(xp, ln1_g + i * HD, ln1_b + i * HD, parts);

        // --- cross-attention (softmax over 1 key == identity -> just Wv, Wout) ---
        k_gemv<<<HD / 8, 256>>>(cawv, cabv, pe, vc, HD, 0);
        k_gemv<<<HD / 8, 256>>>(cow,  cob,  vc, cc, HD, 0);
        k_ln_part <<<16, 256>>>(xp, cc, 1, parts);
        k_ln_apply<<<64, 256>>>(xp, ln2_g + i * HD, ln2_b + i * HD, parts);

        // --- feed-forward ---
        run_gemm(f1w, f1b, xp, t8, 8192, HD, 4, 1, 0, gp);
        run_gemm(f2w, f2b, t8, t2, HD, 8192, 16, 0, 0, gp);
        k_ln_part <<<16, 256>>>(xp, t2, 0, parts);
        k_ln_apply<<<64, 256>>>(xp, ln3_g + i * HD, ln3_b + i * HD, parts);
    }

    // byte logits -> out[33:], row-major [s][256]
    run_gemm(proj_w, proj_b, xp, out + 33, 256, HD, 16, 0, 1, gp);
}